// round 14
// baseline (speedup 1.0000x reference)
#include <cuda_runtime.h>
#include <math.h>
#include <stdint.h>

// Problem constants
#define S_LEN 2048
#define BATCH 2
#define HID   2048
#define NHEAD 16
#define HDIM  128
#define NH_B  (BATCH * NHEAD)   // 32 heads total

// Scratch (device globals: no allocation allowed in kernel_launch)
__device__ float g_q[(size_t)NH_B * S_LEN * HDIM];     // [b*NH+nh][s][hd]
__device__ float g_k[(size_t)NH_B * S_LEN * HDIM];
__device__ float g_v[(size_t)NH_B * S_LEN * HDIM];
__device__ float g_attn[(size_t)S_LEN * BATCH * HID];  // [s][b][h]
__device__ float g_tab[S_LEN * 64 * 2];                // cos/sin table

// ---------------------------------------------------------------------------
// Helpers
// ---------------------------------------------------------------------------
__device__ __forceinline__ uint32_t f2tf(float x) {
    uint32_t r;
    asm("cvt.rna.tf32.f32 %0, %1;" : "=r"(r) : "f"(x));
    return r;
}

__device__ __forceinline__ void mma8(float c[4], const uint32_t a[4],
                                     uint32_t b0, uint32_t b1) {
    asm volatile(
        "mma.sync.aligned.m16n8k8.row.col.f32.tf32.tf32.f32 "
        "{%0,%1,%2,%3}, {%4,%5,%6,%7}, {%8,%9}, {%0,%1,%2,%3};"
        : "+f"(c[0]), "+f"(c[1]), "+f"(c[2]), "+f"(c[3])
        : "r"(a[0]), "r"(a[1]), "r"(a[2]), "r"(a[3]), "r"(b0), "r"(b1));
}

__device__ __forceinline__ void cpa16(uint32_t smem_b, const void* g) {
    asm volatile("cp.async.cg.shared.global [%0], [%1], 16;" :: "r"(smem_b), "l"(g));
}
__device__ __forceinline__ void cpa_commit() {
    asm volatile("cp.async.commit_group;");
}
template<int N>
__device__ __forceinline__ void cpa_wait() {
    asm volatile("cp.async.wait_group %0;" :: "n"(N));
}

__device__ __forceinline__ uint32_t smem_u32(const void* p) {
    uint32_t r;
    asm("{ .reg .u64 t; cvta.to.shared.u64 t, %1; cvt.u32.u64 %0, t; }"
        : "=r"(r) : "l"(p));
    return r;
}

// ---------------------------------------------------------------------------
// GEMM: C[M,N] = A[M,K] * W[N,K]^T, single tf32 (rna).
// Block 256x128x32, 256 threads (8 warps 4x2, warp tile 64x64).
// 4-stage cp.async ring, ONE __syncthreads per k-iter, prefetch distance 2.
// MODE 0: A = hidden_states, scatter into g_q/g_k/g_v; MODE 1: A = g_attn -> C.
// ---------------------------------------------------------------------------
#define GM 256
#define GN 128
#define GK 32
#define GLD 36                       // 32 + pad (conflict-free frag loads)
#define A_FLOATS (GM * GLD)          // 9216
#define B_FLOATS (GN * GLD)          // 4608
#define STAGE_FLOATS (A_FLOATS + B_FLOATS)   // 13824 (55296 B)
#define NSTAGE 4
#define GEMM_SMEM (NSTAGE * STAGE_FLOATS * 4)  // 221184

__device__ __forceinline__ void gemm_stage(uint32_t sbase, int buf,
                                           const float* Ap, const float* W,
                                           int bm, int bn, int K, int kt, int t)
{
    uint32_t a0 = sbase + (uint32_t)(buf * STAGE_FLOATS) * 4u;
    uint32_t b0 = a0 + A_FLOATS * 4u;
    #pragma unroll
    for (int i = 0; i < 8; i++) {
        int ca = t + 256 * i;
        int r = ca >> 3, ch = ca & 7;
        cpa16(a0 + (uint32_t)(r * GLD + ch * 4) * 4u,
              Ap + (size_t)(bm + r) * K + kt + ch * 4);
    }
    #pragma unroll
    for (int i = 0; i < 4; i++) {
        int cb = t + 256 * i;
        int r = cb >> 3, ch = cb & 7;
        cpa16(b0 + (uint32_t)(r * GLD + ch * 4) * 4u,
              W + (size_t)(bn + r) * K + kt + ch * 4);
    }
    cpa_commit();
}

template<int MODE>
__global__ void __launch_bounds__(256)
gemm_kernel(const float* __restrict__ A_, const float* __restrict__ W,
            float* __restrict__ C, int M, int N, int K)
{
    extern __shared__ float sm[];
    const float* Ap = (MODE == 1) ? g_attn : A_;
    const uint32_t sbase = smem_u32(sm);

    const int t = threadIdx.x;
    const int warp = t >> 5, lane = t & 31;
    const int qr = lane >> 2, qc = lane & 3;
    const int bm = blockIdx.y * GM;
    const int bn = blockIdx.x * GN;
    const int wm = (warp >> 1) * 64;
    const int wn = (warp & 1) * 64;
    const int T = K / GK;

    float acc[4][8][4];
    #pragma unroll
    for (int i = 0; i < 4; i++)
        #pragma unroll
        for (int j = 0; j < 8; j++)
            #pragma unroll
            for (int e = 0; e < 4; e++) acc[i][j][e] = 0.f;

    gemm_stage(sbase, 0, Ap, W, bm, bn, K, 0, t);
    gemm_stage(sbase, 1, Ap, W, bm, bn, K, GK, t);

    for (int tt = 0; tt < T; tt++) {
        if (tt + 2 < T) {
            gemm_stage(sbase, (tt + 2) & 3, Ap, W, bm, bn, K, (tt + 2) * GK, t);
            cpa_wait<2>();
        } else if (tt + 1 < T) {
            cpa_wait<1>();
        } else {
            cpa_wait<0>();
        }
        __syncthreads();

        const float* As = sm + (tt & 3) * STAGE_FLOATS;
        const float* Bs = As + A_FLOATS;

        #pragma unroll
        for (int ks = 0; ks < 4; ks++) {
            const int k0 = ks * 8 + qc;
            uint32_t a[4][4];
            #pragma unroll
            for (int mi = 0; mi < 4; mi++) {
                int r = wm + mi * 16 + qr;
                a[mi][0] = f2tf(As[r * GLD + k0]);
                a[mi][1] = f2tf(As[(r + 8) * GLD + k0]);
                a[mi][2] = f2tf(As[r * GLD + k0 + 4]);
                a[mi][3] = f2tf(As[(r + 8) * GLD + k0 + 4]);
            }
            #pragma unroll
            for (int ni = 0; ni < 8; ni++) {
                int cb = wn + ni * 8 + qr;
                uint32_t b0 = f2tf(Bs[cb * GLD + k0]);
                uint32_t b1 = f2tf(Bs[cb * GLD + k0 + 4]);
                #pragma unroll
                for (int mi = 0; mi < 4; mi++)
                    mma8(acc[mi][ni], a[mi], b0, b1);
            }
        }
    }

    // Epilogue
    #pragma unroll
    for (int mi = 0; mi < 4; mi++)
        #pragma unroll
        for (int ni = 0; ni < 8; ni++)
            #pragma unroll
            for (int e = 0; e < 4; e++) {
                int row = bm + wm + mi * 16 + qr + ((e >> 1) << 3);
                int col = bn + wn + ni * 8 + 2 * qc + (e & 1);
                float v = acc[mi][ni][e];
                if (MODE == 0) {
                    int tsel = col >> 11;          // 0=q 1=k 2=v
                    int rem  = col & 2047;
                    int nh = rem >> 7, hd = rem & 127;
                    int s = row >> 1, b = row & 1;
                    float* dst = (tsel == 0) ? g_q : ((tsel == 1) ? g_k : g_v);
                    dst[((size_t)(b * NHEAD + nh) * S_LEN + s) * HDIM + hd] = v;
                } else {
                    C[(size_t)row * N + col] = v;
                }
            }
}

// ---------------------------------------------------------------------------
// RoPE
// ---------------------------------------------------------------------------
__global__ void rope_table_kernel()
{
    int idx = blockIdx.x * blockDim.x + threadIdx.x;   // 2048*64
    int s = idx >> 6, d = idx & 63;
    float e = (float)d * (1.0f / 64.0f);
    float inv = 1.0f / powf(10000.0f, e);
    float th = (float)s * inv;
    double sd, cd;
    sincos((double)th, &sd, &cd);
    g_tab[idx * 2 + 0] = (float)cd;
    g_tab[idx * 2 + 1] = (float)sd;
}

__global__ void rope_apply_kernel()
{
    int i = blockIdx.x * blockDim.x + threadIdx.x;  // 2 * 32 * 2048 * 64
    int d = i & 63;
    int s = (i >> 6) & 2047;
    int h = (i >> 17) & 31;
    int w = i >> 22;
    float c  = g_tab[((s << 6) + d) * 2 + 0];
    float sn = g_tab[((s << 6) + d) * 2 + 1];
    float* buf = w ? g_k : g_q;
    size_t base = ((size_t)h * S_LEN + s) * HDIM;
    float x0 = buf[base + d];
    float x1 = buf[base + d + 64];
    buf[base + d]      = x0 * c - x1 * sn;
    buf[base + d + 64] = x1 * c + x0 * sn;
}

// ---------------------------------------------------------------------------
// Causal flash attention v2:
// 64 q-rows per CTA, 4 warps (128 threads), 2 CTAs/SM.
// KN=32 K/V tiles, cp.async double-buffered (raw fp32, cvt at frag load).
// One __syncthreads per j-iter. Single-tf32 numerics (same as R11).
// ---------------------------------------------------------------------------
#define ALD 132             // Q/K row stride
#define VLD 136             // V row stride
#define PLD 36              // P row stride (KN=32)
#define QOFF 0
#define KOFF (64 * ALD)                 // 8448
#define KBUF (32 * ALD)                 // 4224
#define VOFF (KOFF + 2 * KBUF)          // 16896
#define VBUF (32 * VLD)                 // 4352
#define POFF (VOFF + 2 * VBUF)          // 25600
#define ATTN_FLOATS (POFF + 64 * PLD)   // 27904
#define ATTN_SMEM (ATTN_FLOATS * 4)     // 111616

__device__ __forceinline__ void attn_stage(uint32_t sb, int buf,
                                           const float* kp, const float* vp,
                                           int j, int t)
{
    const float* ks = kp + (size_t)j * 32 * HDIM;
    const float* vs = vp + (size_t)j * 32 * HDIM;
    uint32_t kb = sb + (uint32_t)(KOFF + buf * KBUF) * 4u;
    uint32_t vb = sb + (uint32_t)(VOFF + buf * VBUF) * 4u;
    #pragma unroll
    for (int i = 0; i < 8; i++) {           // 32 rows x 32 chunks (16B)
        int id = t + 128 * i;
        int r = id >> 5, c = id & 31;
        cpa16(kb + (uint32_t)(r * ALD + c * 4) * 4u, ks + r * HDIM + c * 4);
        cpa16(vb + (uint32_t)(r * VLD + c * 4) * 4u, vs + r * HDIM + c * 4);
    }
    cpa_commit();
}

__global__ void __launch_bounds__(128, 2)
attn_kernel()
{
    extern __shared__ float sm[];
    const uint32_t sb = smem_u32(sm);
    float* Qs = sm + QOFF;
    float* Ps = sm + POFF;

    const int t = threadIdx.x, warp = t >> 5, lane = t & 31;
    const int qr = lane >> 2, qc = lane & 3;
    const int qb = gridDim.x - 1 - blockIdx.x;   // heavy CTAs first
    const int hb = blockIdx.y;
    const size_t head_off = (size_t)hb * S_LEN * HDIM;
    const int wrow = warp * 16;
    const float* kp = g_k + head_off;
    const float* vp = g_v + head_off;

    // Load Q tile (64 x 128) as tf32 into smem
    {
        const float* qp = g_q + head_off + (size_t)qb * 64 * HDIM;
        #pragma unroll
        for (int it = 0; it < 16; it++) {
            int i = t * 4 + it * 512;
            int r = i >> 7, c = i & 127;
            float4 v = *(const float4*)(qp + r * 128 + c);
            Qs[r * ALD + c + 0] = __uint_as_float(f2tf(v.x));
            Qs[r * ALD + c + 1] = __uint_as_float(f2tf(v.y));
            Qs[r * ALD + c + 2] = __uint_as_float(f2tf(v.z));
            Qs[r * ALD + c + 3] = __uint_as_float(f2tf(v.w));
        }
    }

    float oacc[16][4];
    #pragma unroll
    for (int i = 0; i < 16; i++)
        #pragma unroll
        for (int e = 0; e < 4; e++) oacc[i][e] = 0.f;
    float m0 = -INFINITY, m1 = -INFINITY, l0 = 0.f, l1 = 0.f;

    const int jmax = 2 * qb + 2;
    attn_stage(sb, 0, kp, vp, 0, t);

    for (int j = 0; j < jmax; j++) {
        cpa_wait<0>();
        __syncthreads();
        if (j + 1 < jmax) attn_stage(sb, (j + 1) & 1, kp, vp, j + 1, t);

        const float* Kc = sm + KOFF + (j & 1) * KBUF;
        const float* Vc = sm + VOFF + (j & 1) * VBUF;

        // ---- S = Q K^T (16 x 32 per warp) ----
        float sacc[4][4];
        #pragma unroll
        for (int nt = 0; nt < 4; nt++)
            #pragma unroll
            for (int e = 0; e < 4; e++) sacc[nt][e] = 0.f;

        #pragma unroll
        for (int ks = 0; ks < 16; ks++) {
            const int k0 = ks * 8 + qc;
            const int r = wrow + qr;
            uint32_t a[4];
            a[0] = __float_as_uint(Qs[r * ALD + k0]);
            a[1] = __float_as_uint(Qs[(r + 8) * ALD + k0]);
            a[2] = __float_as_uint(Qs[r * ALD + k0 + 4]);
            a[3] = __float_as_uint(Qs[(r + 8) * ALD + k0 + 4]);
            #pragma unroll
            for (int nt = 0; nt < 4; nt++) {
                int cr = nt * 8 + qr;
                uint32_t b0 = f2tf(Kc[cr * ALD + k0]);
                uint32_t b1 = f2tf(Kc[cr * ALD + k0 + 4]);
                mma8(sacc[nt], a, b0, b1);
            }
        }

        // ---- scale + causal mask + online softmax ----
        const float scale = 0.08838834764831845f;  // 1/sqrt(128)
        const bool maskt = (j >= 2 * qb);
        const int grow0 = qb * 64 + wrow + qr;
        float mx0 = -INFINITY, mx1 = -INFINITY;
        #pragma unroll
        for (int nt = 0; nt < 4; nt++)
            #pragma unroll
            for (int e = 0; e < 4; e++) {
                float v = sacc[nt][e] * scale;
                if (maskt) {
                    int col = j * 32 + nt * 8 + 2 * qc + (e & 1);
                    int grow = grow0 + ((e >> 1) << 3);
                    if (col > grow) v = -1e30f;
                }
                sacc[nt][e] = v;
                if (e < 2) mx0 = fmaxf(mx0, v); else mx1 = fmaxf(mx1, v);
            }
        mx0 = fmaxf(mx0, __shfl_xor_sync(0xffffffffu, mx0, 1));
        mx0 = fmaxf(mx0, __shfl_xor_sync(0xffffffffu, mx0, 2));
        mx1 = fmaxf(mx1, __shfl_xor_sync(0xffffffffu, mx1, 1));
        mx1 = fmaxf(mx1, __shfl_xor_sync(0xffffffffu, mx1, 2));
        float nm0 = fmaxf(m0, mx0), nm1 = fmaxf(m1, mx1);
        float f0 = __expf(m0 - nm0), f1 = __expf(m1 - nm1);
        float s0 = 0.f, s1 = 0.f;
        #pragma unroll
        for (int nt = 0; nt < 4; nt++)
            #pragma unroll
            for (int e = 0; e < 4; e++) {
                float p = __expf(sacc[nt][e] - ((e < 2) ? nm0 : nm1));
                sacc[nt][e] = p;
                if (e < 2) s0 += p; else s1 += p;
            }
        s0 += __shfl_xor_sync(0xffffffffu, s0, 1);
        s0 += __shfl_xor_sync(0xffffffffu, s0, 2);
        s1 += __shfl_xor_sync(0xffffffffu, s1, 1);
        s1 += __shfl_xor_sync(0xffffffffu, s1, 2);
        l0 = l0 * f0 + s0;
        l1 = l1 * f1 + s1;
        m0 = nm0; m1 = nm1;
        #pragma unroll
        for (int nt = 0; nt < 16; nt++)
            #pragma unroll
            for (int e = 0; e < 4; e++) oacc[nt][e] *= (e < 2) ? f0 : f1;

        // ---- stage P (tf32) into per-warp smem rows ----
        #pragma unroll
        for (int nt = 0; nt < 4; nt++)
            #pragma unroll
            for (int e = 0; e < 4; e++) {
                int r = wrow + qr + ((e >> 1) << 3);
                int c = nt * 8 + 2 * qc + (e & 1);
                Ps[r * PLD + c] = __uint_as_float(f2tf(sacc[nt][e]));
            }
        __syncwarp();

        // ---- O += P V ----
        #pragma unroll
        for (int ks = 0; ks < 4; ks++) {
            const int k0 = ks * 8 + qc;
            const int r = wrow + qr;
            uint32_t a[4];
            a[0] = __float_as_uint(Ps[r * PLD + k0]);
            a[1] = __float_as_uint(Ps[(r + 8) * PLD + k0]);
            a[2] = __float_as_uint(Ps[r * PLD + k0 + 4]);
            a[3] = __float_as_uint(Ps[(r + 8) * PLD + k0 + 4]);
            #pragma unroll
            for (int nt = 0; nt < 16; nt++) {
                uint32_t b0 = f2tf(Vc[k0 * VLD + nt * 8 + qr]);
                uint32_t b1 = f2tf(Vc[(k0 + 4) * VLD + nt * 8 + qr]);
                mma8(oacc[nt], a, b0, b1);
            }
        }
    }

    // ---- finalize: O /= l, write to g_attn [s][b][h] ----
    const float il0 = 1.f / l0, il1 = 1.f / l1;
    const int b = hb >> 4, nh = hb & 15;
    #pragma unroll
    for (int nt = 0; nt < 16; nt++)
        #pragma unroll
        for (int e = 0; e < 4; e++) {
            int srow = qb * 64 + wrow + qr + ((e >> 1) << 3);
            int col  = nt * 8 + 2 * qc + (e & 1);
            float v = oacc[nt][e] * ((e < 2) ? il0 : il1);
            g_attn[((size_t)srow * BATCH + b) * HID + nh * HDIM + col] = v;
        }
}

// ---------------------------------------------------------------------------
// Launch
// ---------------------------------------------------------------------------
extern "C" void kernel_launch(void* const* d_in, const int* in_sizes, int n_in,
                              void* d_out, int out_size)
{
    const float* hs   = (const float*)d_in[0];  // [S,B,H]
    const float* wqkv = (const float*)d_in[1];  // [3H,H]
    const float* wout = (const float*)d_in[2];  // [H,H]
    float* out = (float*)d_out;                 // [S,B,H]

    cudaFuncSetAttribute(gemm_kernel<0>, cudaFuncAttributeMaxDynamicSharedMemorySize, GEMM_SMEM);
    cudaFuncSetAttribute(gemm_kernel<1>, cudaFuncAttributeMaxDynamicSharedMemorySize, GEMM_SMEM);
    cudaFuncSetAttribute(attn_kernel,    cudaFuncAttributeMaxDynamicSharedMemorySize, ATTN_SMEM);

    const int M = S_LEN * BATCH;  // 4096

    // 1) QKV projection (scatter into g_q/g_k/g_v head-major)
    gemm_kernel<0><<<dim3(3 * HID / GN, M / GM), 256, GEMM_SMEM>>>(
        hs, wqkv, nullptr, M, 3 * HID, HID);

    // 2) RoPE table + apply to q,k
    rope_table_kernel<<<(S_LEN * 64) / 256, 256>>>();
    rope_apply_kernel<<<(2 * NH_B * S_LEN * 64) / 256, 256>>>();

    // 3) Causal attention -> g_attn [s][b][h]
    attn_kernel<<<dim3(S_LEN / 64, NH_B), 128, ATTN_SMEM>>>();

    // 4) Output projection -> d_out
    gemm_kernel<1><<<dim3(HID / GN, M / GM), 256, GEMM_SMEM>>>(
        nullptr, wout, out, M, HID, HID);
}

// round 17
// speedup vs baseline: 1.1665x; 1.1665x over previous
#include <cuda_runtime.h>
#include <math.h>
#include <stdint.h>

// Problem constants
#define S_LEN 2048
#define BATCH 2
#define HID   2048
#define NHEAD 16
#define HDIM  128
#define NH_B  (BATCH * NHEAD)   // 32 heads total

// Scratch (device globals: no allocation allowed in kernel_launch)
__device__ float g_q[(size_t)NH_B * S_LEN * HDIM];     // [b*NH+nh][s][hd] tf32-valued
__device__ float g_k[(size_t)NH_B * S_LEN * HDIM];     // tf32-valued
__device__ float g_v[(size_t)NH_B * S_LEN * HDIM];     // tf32-valued
__device__ float g_attn[(size_t)S_LEN * BATCH * HID];  // tf32-valued
__device__ float g_tab[S_LEN * 64 * 2];                // cos/sin table

// tf32-valued copies of the inputs (pre-converted once per launch)
__device__ float g_hsT[(size_t)4096 * 2048];
__device__ float g_wqT[(size_t)6144 * 2048];
__device__ float g_woT[(size_t)2048 * 2048];

// ---------------------------------------------------------------------------
// Helpers
// ---------------------------------------------------------------------------
__device__ __forceinline__ uint32_t f2tf(float x) {
    uint32_t r;
    asm("cvt.rna.tf32.f32 %0, %1;" : "=r"(r) : "f"(x));
    return r;
}

__device__ __forceinline__ void mma8(float c[4], const uint32_t a[4],
                                     uint32_t b0, uint32_t b1) {
    asm volatile(
        "mma.sync.aligned.m16n8k8.row.col.f32.tf32.tf32.f32 "
        "{%0,%1,%2,%3}, {%4,%5,%6,%7}, {%8,%9}, {%0,%1,%2,%3};"
        : "+f"(c[0]), "+f"(c[1]), "+f"(c[2]), "+f"(c[3])
        : "r"(a[0]), "r"(a[1]), "r"(a[2]), "r"(a[3]), "r"(b0), "r"(b1));
}

__device__ __forceinline__ void cpa16(uint32_t smem_b, const void* g) {
    asm volatile("cp.async.cg.shared.global [%0], [%1], 16;" :: "r"(smem_b), "l"(g));
}
__device__ __forceinline__ void cpa_commit() {
    asm volatile("cp.async.commit_group;");
}
template<int N>
__device__ __forceinline__ void cpa_wait() {
    asm volatile("cp.async.wait_group %0;" :: "n"(N));
}

__device__ __forceinline__ uint32_t smem_u32(const void* p) {
    uint32_t r;
    asm("{ .reg .u64 t; cvta.to.shared.u64 t, %1; cvt.u32.u64 %0, t; }"
        : "=r"(r) : "l"(p));
    return r;
}

// ---------------------------------------------------------------------------
// tf32 pre-conversion pass. DST selected in DEVICE code (passing a __device__
// global's address from host is invalid — that was the R15/R16 failure).
// ---------------------------------------------------------------------------
template<int SEL>
__global__ void tf32_conv_kernel(const float* __restrict__ src, int n4)
{
    int i = blockIdx.x * blockDim.x + threadIdx.x;
    if (i >= n4) return;
    float* dst = (SEL == 0) ? g_hsT : (SEL == 1) ? g_wqT : g_woT;
    float4 v = ((const float4*)src)[i];
    v.x = __uint_as_float(f2tf(v.x));
    v.y = __uint_as_float(f2tf(v.y));
    v.z = __uint_as_float(f2tf(v.z));
    v.w = __uint_as_float(f2tf(v.w));
    ((float4*)dst)[i] = v;
}

// ---------------------------------------------------------------------------
// GEMM: C[M,N] = A[M,K] * W[N,K]^T, inputs already tf32-valued fp32.
// Block 256x128x32, 256 threads (8 warps 4x2, warp tile 64x64).
// 4-stage cp.async ring, one __syncthreads per k-iter, prefetch distance 2.
// MODE 0: A=g_hsT, W=g_wqT -> scatter q/k/v (v tf32-rounded).
// MODE 1: A=g_attn (tf32-valued), W=g_woT -> C.
// ---------------------------------------------------------------------------
#define GM 256
#define GN 128
#define GK 32
#define GLD 36
#define A_FLOATS (GM * GLD)
#define B_FLOATS (GN * GLD)
#define STAGE_FLOATS (A_FLOATS + B_FLOATS)     // 13824
#define NSTAGE 4
#define GEMM_SMEM (NSTAGE * STAGE_FLOATS * 4)  // 221184

__device__ __forceinline__ void gemm_stage(uint32_t sbase, int buf,
                                           const float* Ap, const float* W,
                                           int bm, int bn, int K, int kt, int t)
{
    uint32_t a0 = sbase + (uint32_t)(buf * STAGE_FLOATS) * 4u;
    uint32_t b0 = a0 + A_FLOATS * 4u;
    #pragma unroll
    for (int i = 0; i < 8; i++) {
        int ca = t + 256 * i;
        int r = ca >> 3, ch = ca & 7;
        cpa16(a0 + (uint32_t)(r * GLD + ch * 4) * 4u,
              Ap + (size_t)(bm + r) * K + kt + ch * 4);
    }
    #pragma unroll
    for (int i = 0; i < 4; i++) {
        int cb = t + 256 * i;
        int r = cb >> 3, ch = cb & 7;
        cpa16(b0 + (uint32_t)(r * GLD + ch * 4) * 4u,
              W + (size_t)(bn + r) * K + kt + ch * 4);
    }
    cpa_commit();
}

template<int MODE>
__global__ void __launch_bounds__(256)
gemm_kernel(float* __restrict__ C, int M, int N, int K)
{
    extern __shared__ float sm[];
    const float* Ap = (MODE == 1) ? g_attn : g_hsT;
    const float* W  = (MODE == 1) ? g_woT  : g_wqT;
    const uint32_t sbase = smem_u32(sm);

    const int t = threadIdx.x;
    const int warp = t >> 5, lane = t & 31;
    const int qr = lane >> 2, qc = lane & 3;
    const int bm = blockIdx.y * GM;
    const int bn = blockIdx.x * GN;
    const int wm = (warp >> 1) * 64;
    const int wn = (warp & 1) * 64;
    const int T = K / GK;

    float acc[4][8][4];
    #pragma unroll
    for (int i = 0; i < 4; i++)
        #pragma unroll
        for (int j = 0; j < 8; j++)
            #pragma unroll
            for (int e = 0; e < 4; e++) acc[i][j][e] = 0.f;

    gemm_stage(sbase, 0, Ap, W, bm, bn, K, 0, t);
    gemm_stage(sbase, 1, Ap, W, bm, bn, K, GK, t);

    for (int tt = 0; tt < T; tt++) {
        if (tt + 2 < T) {
            gemm_stage(sbase, (tt + 2) & 3, Ap, W, bm, bn, K, (tt + 2) * GK, t);
            cpa_wait<2>();
        } else if (tt + 1 < T) {
            cpa_wait<1>();
        } else {
            cpa_wait<0>();
        }
        __syncthreads();

        const float* As = sm + (tt & 3) * STAGE_FLOATS;
        const float* Bs = As + A_FLOATS;

        #pragma unroll
        for (int ks = 0; ks < 4; ks++) {
            const int k0 = ks * 8 + qc;
            uint32_t a[4][4];
            #pragma unroll
            for (int mi = 0; mi < 4; mi++) {
                int r = wm + mi * 16 + qr;
                a[mi][0] = __float_as_uint(As[r * GLD + k0]);
                a[mi][1] = __float_as_uint(As[(r + 8) * GLD + k0]);
                a[mi][2] = __float_as_uint(As[r * GLD + k0 + 4]);
                a[mi][3] = __float_as_uint(As[(r + 8) * GLD + k0 + 4]);
            }
            #pragma unroll
            for (int ni = 0; ni < 8; ni++) {
                int cb = wn + ni * 8 + qr;
                uint32_t b0 = __float_as_uint(Bs[cb * GLD + k0]);
                uint32_t b1 = __float_as_uint(Bs[cb * GLD + k0 + 4]);
                #pragma unroll
                for (int mi = 0; mi < 4; mi++)
                    mma8(acc[mi][ni], a[mi], b0, b1);
            }
        }
    }

    // Epilogue
    #pragma unroll
    for (int mi = 0; mi < 4; mi++)
        #pragma unroll
        for (int ni = 0; ni < 8; ni++)
            #pragma unroll
            for (int e = 0; e < 4; e++) {
                int row = bm + wm + mi * 16 + qr + ((e >> 1) << 3);
                int col = bn + wn + ni * 8 + 2 * qc + (e & 1);
                float v = acc[mi][ni][e];
                if (MODE == 0) {
                    int tsel = col >> 11;          // 0=q 1=k 2=v
                    int rem  = col & 2047;
                    int nh = rem >> 7, hd = rem & 127;
                    int s = row >> 1, b = row & 1;
                    float* dst = (tsel == 0) ? g_q : ((tsel == 1) ? g_k : g_v);
                    if (tsel == 2) v = __uint_as_float(f2tf(v));  // pre-round V
                    dst[((size_t)(b * NHEAD + nh) * S_LEN + s) * HDIM + hd] = v;
                } else {
                    C[(size_t)row * N + col] = v;
                }
            }
}

// ---------------------------------------------------------------------------
// RoPE (writes tf32-rounded q/k so attention consumes them raw)
// ---------------------------------------------------------------------------
__global__ void rope_table_kernel()
{
    int idx = blockIdx.x * blockDim.x + threadIdx.x;   // 2048*64
    int s = idx >> 6, d = idx & 63;
    float e = (float)d * (1.0f / 64.0f);
    float inv = 1.0f / powf(10000.0f, e);
    float th = (float)s * inv;
    double sd, cd;
    sincos((double)th, &sd, &cd);
    g_tab[idx * 2 + 0] = (float)cd;
    g_tab[idx * 2 + 1] = (float)sd;
}

__global__ void rope_apply_kernel()
{
    int i = blockIdx.x * blockDim.x + threadIdx.x;  // 2 * 32 * 2048 * 64
    int d = i & 63;
    int s = (i >> 6) & 2047;
    int h = (i >> 17) & 31;
    int w = i >> 22;
    float c  = g_tab[((s << 6) + d) * 2 + 0];
    float sn = g_tab[((s << 6) + d) * 2 + 1];
    float* buf = w ? g_k : g_q;
    size_t base = ((size_t)h * S_LEN + s) * HDIM;
    float x0 = buf[base + d];
    float x1 = buf[base + d + 64];
    buf[base + d]      = __uint_as_float(f2tf(x0 * c - x1 * sn));
    buf[base + d + 64] = __uint_as_float(f2tf(x1 * c + x0 * sn));
}

// ---------------------------------------------------------------------------
// Causal flash attention v4 (R11 structure + cp.async staging):
// 256 threads, 8 warps x 16 full q-rows, 128 q-rows/CTA, KN=64.
// V double-buffered (full-iter latency hiding), K single-buffered restaged
// mid-iteration (hidden behind PV). All operands pre-rounded tf32 values.
// ---------------------------------------------------------------------------
#define ALD 132
#define VLD 136
#define PLD 68
#define QOFF 0
#define KOFF (128 * ALD)                 // 16896
#define VOFF (KOFF + 64 * ALD)           // 25344
#define VBUF (64 * VLD)                  // 8704
#define POFF (VOFF + 2 * VBUF)           // 42752
#define ATTN_FLOATS (POFF + 128 * PLD)   // 51456
#define ATTN_SMEM (ATTN_FLOATS * 4)      // 205824

__device__ __forceinline__ void attn_stage_k(uint32_t sb, const float* kp,
                                             int j, int t)
{
    const float* ks = kp + (size_t)j * 64 * HDIM;
    #pragma unroll
    for (int i = 0; i < 8; i++) {           // 64 rows x 32 chunks (16B)
        int id = t + 256 * i;
        int r = id >> 5, c = id & 31;
        cpa16(sb + (uint32_t)(KOFF + r * ALD + c * 4) * 4u, ks + r * HDIM + c * 4);
    }
    cpa_commit();
}
__device__ __forceinline__ void attn_stage_v(uint32_t sb, int buf,
                                             const float* vp, int j, int t)
{
    const float* vs = vp + (size_t)j * 64 * HDIM;
    #pragma unroll
    for (int i = 0; i < 8; i++) {
        int id = t + 256 * i;
        int r = id >> 5, c = id & 31;
        cpa16(sb + (uint32_t)(VOFF + buf * VBUF + r * VLD + c * 4) * 4u,
              vs + r * HDIM + c * 4);
    }
    cpa_commit();
}

__global__ void __launch_bounds__(256, 1)
attn_kernel()
{
    extern __shared__ float sm[];
    const uint32_t sb = smem_u32(sm);
    float* Qs = sm + QOFF;
    float* Ks = sm + KOFF;
    float* Ps = sm + POFF;

    const int t = threadIdx.x, warp = t >> 5, lane = t & 31;
    const int qr = lane >> 2, qc = lane & 3;
    const int qb = gridDim.x - 1 - blockIdx.x;   // heavy CTAs first
    const int hb = blockIdx.y;
    const size_t head_off = (size_t)hb * S_LEN * HDIM;
    const int wrow = warp * 16;
    const float* kp = g_k + head_off;
    const float* vp = g_v + head_off;

    // Load Q tile (128 x 128), already tf32-valued
    {
        const float* qp = g_q + head_off + (size_t)qb * 128 * HDIM;
        #pragma unroll
        for (int it = 0; it < 16; it++) {
            int i = t * 4 + it * 1024;
            int r = i >> 7, c = i & 127;
            float4 v = *(const float4*)(qp + r * 128 + c);
            *(float4*)(Qs + r * ALD + c) = v;
        }
    }

    float oacc[16][4];
    #pragma unroll
    for (int i = 0; i < 16; i++)
        #pragma unroll
        for (int e = 0; e < 4; e++) oacc[i][e] = 0.f;
    float m0 = -INFINITY, m1 = -INFINITY, l0 = 0.f, l1 = 0.f;

    const int jmax = 2 * qb + 2;
    attn_stage_v(sb, 0, vp, 0, t);
    attn_stage_k(sb, kp, 0, t);

    for (int j = 0; j < jmax; j++) {
        cpa_wait<0>();
        __syncthreads();   // K(j) and V(j) resident; all warps past prior iter

        // Prefetch V(j+1) into the other buffer (full iteration to land)
        if (j + 1 < jmax) attn_stage_v(sb, (j + 1) & 1, vp, j + 1, t);

        const float* Vc = sm + VOFF + (j & 1) * VBUF;

        // ---- S = Q K^T: 16 rows x 64 cols per warp ----
        float sacc[8][4];
        #pragma unroll
        for (int nt = 0; nt < 8; nt++)
            #pragma unroll
            for (int e = 0; e < 4; e++) sacc[nt][e] = 0.f;

        #pragma unroll
        for (int ks = 0; ks < 16; ks++) {
            const int k0 = ks * 8 + qc;
            const int r = wrow + qr;
            uint32_t a[4];
            a[0] = __float_as_uint(Qs[r * ALD + k0]);
            a[1] = __float_as_uint(Qs[(r + 8) * ALD + k0]);
            a[2] = __float_as_uint(Qs[r * ALD + k0 + 4]);
            a[3] = __float_as_uint(Qs[(r + 8) * ALD + k0 + 4]);
            #pragma unroll
            for (int nt = 0; nt < 8; nt++) {
                int cr = nt * 8 + qr;
                uint32_t b0 = __float_as_uint(Ks[cr * ALD + k0]);
                uint32_t b1 = __float_as_uint(Ks[cr * ALD + k0 + 4]);
                mma8(sacc[nt], a, b0, b1);
            }
        }

        // ---- scale + causal mask + online softmax (per-warp) ----
        const float scale = 0.08838834764831845f;  // 1/sqrt(128)
        const bool maskt = (j >= 2 * qb);
        const int grow0 = qb * 128 + wrow + qr;
        float mx0 = -INFINITY, mx1 = -INFINITY;
        #pragma unroll
        for (int nt = 0; nt < 8; nt++)
            #pragma unroll
            for (int e = 0; e < 4; e++) {
                float v = sacc[nt][e] * scale;
                if (maskt) {
                    int col = j * 64 + nt * 8 + 2 * qc + (e & 1);
                    int grow = grow0 + ((e >> 1) << 3);
                    if (col > grow) v = -1e30f;
                }
                sacc[nt][e] = v;
                if (e < 2) mx0 = fmaxf(mx0, v); else mx1 = fmaxf(mx1, v);
            }
        mx0 = fmaxf(mx0, __shfl_xor_sync(0xffffffffu, mx0, 1));
        mx0 = fmaxf(mx0, __shfl_xor_sync(0xffffffffu, mx0, 2));
        mx1 = fmaxf(mx1, __shfl_xor_sync(0xffffffffu, mx1, 1));
        mx1 = fmaxf(mx1, __shfl_xor_sync(0xffffffffu, mx1, 2));
        float nm0 = fmaxf(m0, mx0), nm1 = fmaxf(m1, mx1);
        float f0 = __expf(m0 - nm0), f1 = __expf(m1 - nm1);
        float s0 = 0.f, s1 = 0.f;
        #pragma unroll
        for (int nt = 0; nt < 8; nt++)
            #pragma unroll
            for (int e = 0; e < 4; e++) {
                float p = __expf(sacc[nt][e] - ((e < 2) ? nm0 : nm1));
                sacc[nt][e] = p;
                if (e < 2) s0 += p; else s1 += p;
            }
        s0 += __shfl_xor_sync(0xffffffffu, s0, 1);
        s0 += __shfl_xor_sync(0xffffffffu, s0, 2);
        s1 += __shfl_xor_sync(0xffffffffu, s1, 1);
        s1 += __shfl_xor_sync(0xffffffffu, s1, 2);
        l0 = l0 * f0 + s0;
        l1 = l1 * f1 + s1;
        m0 = nm0; m1 = nm1;
        #pragma unroll
        for (int nt = 0; nt < 16; nt++)
            #pragma unroll
            for (int e = 0; e < 4; e++) oacc[nt][e] *= (e < 2) ? f0 : f1;

        // ---- stage P (tf32-rounded) into own-warp smem rows ----
        #pragma unroll
        for (int nt = 0; nt < 8; nt++)
            #pragma unroll
            for (int e = 0; e < 4; e++) {
                int r = wrow + qr + ((e >> 1) << 3);
                int c = nt * 8 + 2 * qc + (e & 1);
                Ps[r * PLD + c] = __uint_as_float(f2tf(sacc[nt][e]));
            }

        // All warps done reading Ks -> restage K(j+1), hidden behind PV
        __syncthreads();
        if (j + 1 < jmax) attn_stage_k(sb, kp, j + 1, t);
        __syncwarp();

        // ---- O += P V (own rows; V raw tf32-valued) ----
        #pragma unroll
        for (int ks = 0; ks < 8; ks++) {
            const int k0 = ks * 8 + qc;
            const int r = wrow + qr;
            uint32_t a[4];
            a[0] = __float_as_uint(Ps[r * PLD + k0]);
            a[1] = __float_as_uint(Ps[(r + 8) * PLD + k0]);
            a[2] = __float_as_uint(Ps[r * PLD + k0 + 4]);
            a[3] = __float_as_uint(Ps[(r + 8) * PLD + k0 + 4]);
            #pragma unroll
            for (int nt = 0; nt < 16; nt++) {
                uint32_t b0 = __float_as_uint(Vc[k0 * VLD + nt * 8 + qr]);
                uint32_t b1 = __float_as_uint(Vc[(k0 + 4) * VLD + nt * 8 + qr]);
                mma8(oacc[nt], a, b0, b1);
            }
        }
    }

    // ---- finalize: O /= l, write tf32-rounded to g_attn [s][b][h] ----
    const float il0 = 1.f / l0, il1 = 1.f / l1;
    const int b = hb >> 4, nh = hb & 15;
    #pragma unroll
    for (int nt = 0; nt < 16; nt++)
        #pragma unroll
        for (int e = 0; e < 4; e++) {
            int srow = qb * 128 + wrow + qr + ((e >> 1) << 3);
            int col  = nt * 8 + 2 * qc + (e & 1);
            float v = oacc[nt][e] * ((e < 2) ? il0 : il1);
            g_attn[((size_t)srow * BATCH + b) * HID + nh * HDIM + col] =
                __uint_as_float(f2tf(v));
        }
}

// ---------------------------------------------------------------------------
// Launch
// ---------------------------------------------------------------------------
extern "C" void kernel_launch(void* const* d_in, const int* in_sizes, int n_in,
                              void* d_out, int out_size)
{
    const float* hs   = (const float*)d_in[0];  // [S,B,H]
    const float* wqkv = (const float*)d_in[1];  // [3H,H]
    const float* wout = (const float*)d_in[2];  // [H,H]
    float* out = (float*)d_out;                 // [S,B,H]

    cudaFuncSetAttribute(gemm_kernel<0>, cudaFuncAttributeMaxDynamicSharedMemorySize, GEMM_SMEM);
    cudaFuncSetAttribute(gemm_kernel<1>, cudaFuncAttributeMaxDynamicSharedMemorySize, GEMM_SMEM);
    cudaFuncSetAttribute(attn_kernel,    cudaFuncAttributeMaxDynamicSharedMemorySize, ATTN_SMEM);

    const int M = S_LEN * BATCH;  // 4096

    // 0) Pre-convert inputs to tf32-valued fp32 (dst chosen in device code!)
    tf32_conv_kernel<0><<<(4096 * 2048 / 4) / 256, 256>>>(hs,   4096 * 2048 / 4);
    tf32_conv_kernel<1><<<(6144 * 2048 / 4) / 256, 256>>>(wqkv, 6144 * 2048 / 4);
    tf32_conv_kernel<2><<<(2048 * 2048 / 4) / 256, 256>>>(wout, 2048 * 2048 / 4);

    // 1) QKV projection (scatter into g_q/g_k/g_v head-major; v tf32-rounded)
    gemm_kernel<0><<<dim3(3 * HID / GN, M / GM), 256, GEMM_SMEM>>>(
        nullptr, M, 3 * HID, HID);

    // 2) RoPE table + apply to q,k (writes tf32-rounded)
    rope_table_kernel<<<(S_LEN * 64) / 256, 256>>>();
    rope_apply_kernel<<<(2 * NH_B * S_LEN * 64) / 256, 256>>>();

    // 3) Causal attention -> g_attn (tf32-rounded)
    attn_kernel<<<dim3(S_LEN / 128, NH_B), 256, ATTN_SMEM>>>();

    // 4) Output projection -> d_out
    gemm_kernel<1><<<dim3(HID / GN, M / GM), 256, GEMM_SMEM>>>(
        out, M, HID, HID);
}